// round 13
// baseline (speedup 1.0000x reference)
#include <cuda_runtime.h>
#include <cuda_bf16.h>
#include <cstdint>
#include <math.h>

// Problem constants
constexpr int Bb = 2;
constexpr int Nn = 4096;
constexpr int Cc = 256;
constexpr int Hh = 8;
constexpr int Mm = 1024;      // reduced tokens (32x32)
constexpr int Kc = 1024;      // conv-as-GEMM K (4 * 256)
constexpr long BMC = (long)Bb * Mm * Cc;
constexpr long XR_PART = (long)2 * Bb * Mm * Cc;   // split-K partial stride

// -------- scratch (static device allocations; no cudaMalloc allowed) --------
__device__ float g_xr  [4 * 2 * Bb * Mm * Cc];  // conv partials (split-K x4)

__device__ __nv_bfloat16 g_x1h [Bb * Nn * Cc];      // x1 split
__device__ __nv_bfloat16 g_x1l [Bb * Nn * Cc];
__device__ __nv_bfloat16 g_gah [2 * Bb * Mm * Kc];  // gathered patches split
__device__ __nv_bfloat16 g_gal [2 * Bb * Mm * Kc];
__device__ __nv_bfloat16 g_srh [Cc * Kc];           // packed sr_w split
__device__ __nv_bfloat16 g_srl [Cc * Kc];
__device__ __nv_bfloat16 g_xrh [2 * Bb * Mm * Cc];  // post-LN split
__device__ __nv_bfloat16 g_xrl [2 * Bb * Mm * Cc];
__device__ __nv_bfloat16 g_qh  [Bb * Nn * Cc];      // q split (from q GEMM)
__device__ __nv_bfloat16 g_ql  [Bb * Nn * Cc];
__device__ __nv_bfloat16 g_kvh [2 * Bb * Mm * Cc];  // [0]: k2, [1]: v1  (hi)
__device__ __nv_bfloat16 g_kvl [2 * Bb * Mm * Cc];  // (lo)
__device__ __nv_bfloat16 g_ath [Bb * Nn * Cc];      // attention out split
__device__ __nv_bfloat16 g_atl [Bb * Nn * Cc];
__device__ __nv_bfloat16 g_qwh [Cc * Cc];
__device__ __nv_bfloat16 g_qwl [Cc * Cc];
__device__ __nv_bfloat16 g_kwh [2 * Cc * Cc];
__device__ __nv_bfloat16 g_kwl [2 * Cc * Cc];
__device__ __nv_bfloat16 g_pwh [Cc * Cc];
__device__ __nv_bfloat16 g_pwl [Cc * Cc];

// ---------------------------------------------------------------------------
__device__ __forceinline__ uint32_t smem_u32(const void* p) {
    uint32_t a;
    asm("{ .reg .u64 t; cvta.to.shared.u64 t, %1; cvt.u32.u64 %0, t; }"
        : "=r"(a) : "l"(p));
    return a;
}
__device__ __forceinline__ void split2(float v, __nv_bfloat16& h, __nv_bfloat16& l) {
    h = __float2bfloat16(v);
    l = __float2bfloat16(v - __bfloat162float(h));
}
__device__ __forceinline__ uint32_t pack_split_hi(float a, float b) {
    __nv_bfloat162 p;
    p.x = __float2bfloat16(a);
    p.y = __float2bfloat16(b);
    return *(uint32_t*)&p;
}
__device__ __forceinline__ uint32_t pack_split_lo(float a, float b) {
    __nv_bfloat162 p;
    p.x = __float2bfloat16(a - __bfloat162float(__float2bfloat16(a)));
    p.y = __float2bfloat16(b - __bfloat162float(__float2bfloat16(b)));
    return *(uint32_t*)&p;
}
__device__ __forceinline__ void split4_at(const float* __restrict__ in,
                                          __nv_bfloat16* __restrict__ oh,
                                          __nv_bfloat16* __restrict__ ol, int idx) {
    float4 v = ((const float4*)in)[idx];
    ((uint32_t*)oh)[idx * 2]     = pack_split_hi(v.x, v.y);
    ((uint32_t*)oh)[idx * 2 + 1] = pack_split_hi(v.z, v.w);
    ((uint32_t*)ol)[idx * 2]     = pack_split_lo(v.x, v.y);
    ((uint32_t*)ol)[idx * 2 + 1] = pack_split_lo(v.z, v.w);
}

#define LDSM_X4(r0, r1, r2, r3, addr) \
    asm volatile("ldmatrix.sync.aligned.m8n8.x4.shared.b16 {%0,%1,%2,%3}, [%4];" \
                 : "=r"(r0), "=r"(r1), "=r"(r2), "=r"(r3) : "r"(addr))

#define LDSM_X4_T(r0, r1, r2, r3, addr) \
    asm volatile("ldmatrix.sync.aligned.m8n8.x4.trans.shared.b16 {%0,%1,%2,%3}, [%4];" \
                 : "=r"(r0), "=r"(r1), "=r"(r2), "=r"(r3) : "r"(addr))

#define MMA_BF16(c, a, b) \
    asm volatile("mma.sync.aligned.m16n8k16.row.col.f32.bf16.bf16.f32 " \
                 "{%0,%1,%2,%3}, {%4,%5,%6,%7}, {%8,%9}, {%0,%1,%2,%3};" \
                 : "+f"((c)[0]), "+f"((c)[1]), "+f"((c)[2]), "+f"((c)[3]) \
                 : "r"((a)[0]), "r"((a)[1]), "r"((a)[2]), "r"((a)[3]), \
                   "r"((b)[0]), "r"((b)[1]))

#define CP16(s, g) \
    asm volatile("cp.async.cg.shared.global [%0], [%1], 16;" :: "r"(s), "l"(g))
#define CP_COMMIT() asm volatile("cp.async.commit_group;" ::: "memory")
#define CP_WAIT0()  asm volatile("cp.async.wait_group 0;" ::: "memory")

// ---------------------------------------------------------------------------
// Fused prep: pack+split sr_w, split q_w/kv_w/proj_w, gather patches,
// split x1. One launch, 7424 blocks.
// ---------------------------------------------------------------------------
__global__ void prep_all_kernel(const float* __restrict__ srw,
                                const float* __restrict__ qw,
                                const float* __restrict__ kvw,
                                const float* __restrict__ pw,
                                const float* __restrict__ x1,
                                const float* __restrict__ x2) {
    int bx = blockIdx.x, t = threadIdx.x;
    if (bx < 1024) {                       // pack sr_w
        int idx = bx * 256 + t;
        int co = idx >> 10;
        int k  = idx & 1023;
        int seg = k >> 8;
        int ci  = k & 255;
        float v = srw[((co << 8) + ci) * 4 + seg];
        __nv_bfloat16 h, l;
        split2(v, h, l);
        g_srh[idx] = h;
        g_srl[idx] = l;
    } else if (bx < 1088) {
        split4_at(qw, g_qwh, g_qwl, (bx - 1024) * 256 + t);
    } else if (bx < 1216) {
        split4_at(kvw, g_kwh, g_kwl, (bx - 1088) * 256 + t);
    } else if (bx < 1280) {
        split4_at(pw, g_pwh, g_pwl, (bx - 1216) * 256 + t);
    } else if (bx < 5376) {                // gather conv patches
        unsigned idx = (bx - 1280) * 256 + t;
        int k4  = idx & 255;
        int m   = (idx >> 8) & 1023;
        int b   = (idx >> 18) & 1;
        int src = (idx >> 19) & 1;
        int seg = k4 >> 6;
        int ci4 = k4 & 63;
        int i = m >> 5, j = m & 31;
        int kh = seg >> 1, kw = seg & 1;
        int n = (2 * i + kh) * 64 + 2 * j + kw;
        const float* sp = src ? x2 : x1;
        float4 v = *(const float4*)(sp + ((long)b * Nn + n) * Cc + ci4 * 4);
        ((uint32_t*)g_gah)[idx * 2]     = pack_split_hi(v.x, v.y);
        ((uint32_t*)g_gah)[idx * 2 + 1] = pack_split_hi(v.z, v.w);
        ((uint32_t*)g_gal)[idx * 2]     = pack_split_lo(v.x, v.y);
        ((uint32_t*)g_gal)[idx * 2 + 1] = pack_split_lo(v.z, v.w);
    } else {                               // split x1
        split4_at(x1, g_x1h, g_x1l, (bx - 5376) * 256 + t);
    }
}

// ---------------------------------------------------------------------------
// mma.sync GEMM (R11/R12): CTA 128x64, cp.async double-buffered,
// one barrier per chunk. Split-K via Kext<Kstride + z offsets.
// ---------------------------------------------------------------------------
constexpr int AST = 40;             // smem stride in halves (80B rows)
constexpr int GA_BUF = 128 * AST;   // 5120 halves per A buffer
constexpr int GW_BUF = 64 * AST;    // 2560 halves per W buffer
constexpr int SM_AL = 2 * GA_BUF;
constexpr int SM_WH = 4 * GA_BUF;
constexpr int SM_WL = SM_WH + 2 * GW_BUF;
constexpr int SM_BIAS_H = SM_WL + 2 * GW_BUF;        // 30720 halves
constexpr int GEMM_SMEM = SM_BIAS_H * 2 + 64 * 4;    // 61696 bytes

template <bool SPLIT>
__global__ __launch_bounds__(256) void gemm_mma_kernel(
    const __nv_bfloat16* __restrict__ Ah, const __nv_bfloat16* __restrict__ Al,
    const __nv_bfloat16* __restrict__ Wh, const __nv_bfloat16* __restrict__ Wl,
    const float* __restrict__ bias, float* __restrict__ Cout,
    __nv_bfloat16* __restrict__ Ch, __nv_bfloat16* __restrict__ Cl,
    int Ndim, int Kext, int Kstride, long sA, long sW, long sC)
{
    extern __shared__ __nv_bfloat16 smem[];
    float* sbias = (float*)(smem + SM_BIAS_H);

    long zo = (long)blockIdx.z;
    Ah += zo * sA; Al += zo * sA;
    Wh += zo * sW; Wl += zo * sW;
    if (SPLIT) { Ch += zo * sC; Cl += zo * sC; }
    else if (Cout) Cout += zo * sC;

    int tid = threadIdx.x, lane = tid & 31, wid = tid >> 5;
    int wm = wid >> 1, wn = wid & 1;
    int m0 = blockIdx.x * 128, n0 = blockIdx.y * 64;

    if (tid < 64) sbias[tid] = (bias && blockIdx.z == 0) ? bias[n0 + tid] : 0.f;

    float acc[2][4][4];
#pragma unroll
    for (int mt = 0; mt < 2; mt++)
#pragma unroll
        for (int nt = 0; nt < 4; nt++)
#pragma unroll
            for (int e = 0; e < 4; e++) acc[mt][nt][e] = 0.f;

    int a_row  = wm * 32 + (lane & 15);
    int a_colb = (lane >> 4) << 3;
    int b_row  = wn * 32 + ((lane >> 4) << 3) + (lane & 7);
    int b_colb = ((lane >> 3) & 1) << 3;

    uint32_t sb = smem_u32(smem);

    int ar = tid >> 1, ahalf = tid & 1;
    int brr = tid >> 2, bq = tid & 3;

    const __nv_bfloat16* gAh = Ah + (size_t)(m0 + ar) * Kstride + ahalf * 16;
    const __nv_bfloat16* gAl = Al + (size_t)(m0 + ar) * Kstride + ahalf * 16;
    const __nv_bfloat16* gWh = Wh + (size_t)(n0 + brr) * Kstride + bq * 8;
    const __nv_bfloat16* gWl = Wl + (size_t)(n0 + brr) * Kstride + bq * 8;

    uint32_t sAh0 = sb + (ar * AST + ahalf * 16) * 2;
    uint32_t sAl0 = sb + (SM_AL + ar * AST + ahalf * 16) * 2;
    uint32_t sWh0 = sb + (SM_WH + brr * AST + bq * 8) * 2;
    uint32_t sWl0 = sb + (SM_WL + brr * AST + bq * 8) * 2;

#define GEMM_ISSUE(k0, buf) do { \
        uint32_t ao = (uint32_t)(buf) * GA_BUF * 2; \
        uint32_t wo = (uint32_t)(buf) * GW_BUF * 2; \
        CP16(sAh0 + ao,      gAh + (k0)); \
        CP16(sAh0 + ao + 16, gAh + (k0) + 8); \
        CP16(sAl0 + ao,      gAl + (k0)); \
        CP16(sAl0 + ao + 16, gAl + (k0) + 8); \
        CP16(sWh0 + wo,      gWh + (k0)); \
        CP16(sWl0 + wo,      gWl + (k0)); \
        CP_COMMIT(); \
    } while (0)

    GEMM_ISSUE(0, 0);

    int nch = Kext >> 5;
    for (int ch = 0; ch < nch; ch++) {
        CP_WAIT0();
        __syncthreads();
        if (ch + 1 < nch) GEMM_ISSUE((ch + 1) * 32, (ch + 1) & 1);

        int buf = ch & 1;
        uint32_t sa_h = sb + (uint32_t)buf * GA_BUF * 2;
        uint32_t sa_l = sb + (SM_AL + buf * GA_BUF) * 2;
        uint32_t sb_h = sb + (SM_WH + buf * GW_BUF) * 2;
        uint32_t sb_l = sb + (SM_WL + buf * GW_BUF) * 2;

#pragma unroll
        for (int ks = 0; ks < 32; ks += 16) {
            uint32_t aH[2][4], aL[2][4], bH[4][2], bL[4][2];
#pragma unroll
            for (int mt = 0; mt < 2; mt++) {
                uint32_t off = (uint32_t)(((a_row + mt * 16) * AST + ks + a_colb) * 2);
                LDSM_X4(aH[mt][0], aH[mt][1], aH[mt][2], aH[mt][3], sa_h + off);
                LDSM_X4(aL[mt][0], aL[mt][1], aL[mt][2], aL[mt][3], sa_l + off);
            }
#pragma unroll
            for (int p = 0; p < 2; p++) {
                uint32_t off = (uint32_t)(((b_row + p * 16) * AST + ks + b_colb) * 2);
                uint32_t r0, r1, r2, r3;
                LDSM_X4(r0, r1, r2, r3, sb_h + off);
                bH[p * 2][0] = r0; bH[p * 2][1] = r1;
                bH[p * 2 + 1][0] = r2; bH[p * 2 + 1][1] = r3;
                LDSM_X4(r0, r1, r2, r3, sb_l + off);
                bL[p * 2][0] = r0; bL[p * 2][1] = r1;
                bL[p * 2 + 1][0] = r2; bL[p * 2 + 1][1] = r3;
            }
#pragma unroll
            for (int mt = 0; mt < 2; mt++)
#pragma unroll
                for (int nt = 0; nt < 4; nt++) {
                    MMA_BF16(acc[mt][nt], aH[mt], bH[nt]);
                    MMA_BF16(acc[mt][nt], aH[mt], bL[nt]);
                    MMA_BF16(acc[mt][nt], aL[mt], bH[nt]);
                }
        }
    }

    int g = lane >> 2, tig = lane & 3;
#pragma unroll
    for (int mt = 0; mt < 2; mt++)
#pragma unroll
        for (int hf = 0; hf < 2; hf++) {
            int row = m0 + wm * 32 + mt * 16 + g + hf * 8;
#pragma unroll
            for (int nt = 0; nt < 4; nt++) {
                int cb = wn * 32 + nt * 8 + tig * 2;
                float ox = acc[mt][nt][hf * 2 + 0] + sbias[cb];
                float oy = acc[mt][nt][hf * 2 + 1] + sbias[cb + 1];
                size_t e = (size_t)row * Ndim + n0 + cb;
                if (SPLIT) {
                    *(uint32_t*)(Ch + e) = pack_split_hi(ox, oy);
                    *(uint32_t*)(Cl + e) = pack_split_lo(ox, oy);
                } else {
                    float2 o; o.x = ox; o.y = oy;
                    *(float2*)(Cout + e) = o;
                }
            }
        }
}

// ---------------------------------------------------------------------------
// LayerNorm over rows (4096 x 256); sums 4 split-K conv partials, -> splits.
// ---------------------------------------------------------------------------
__global__ __launch_bounds__(256) void layernorm_kernel(
    const float* __restrict__ g, const float* __restrict__ b)
{
    int warp = threadIdx.x >> 5, lane = threadIdx.x & 31;
    long row = (long)blockIdx.x * 8 + warp;

    float4 v0 = make_float4(0.f, 0.f, 0.f, 0.f);
    float4 v1 = make_float4(0.f, 0.f, 0.f, 0.f);
#pragma unroll
    for (int part = 0; part < 4; part++) {
        const float* p = g_xr + part * XR_PART + row * 256;
        float4 a0 = ((const float4*)p)[lane];
        float4 a1 = ((const float4*)p)[lane + 32];
        v0.x += a0.x; v0.y += a0.y; v0.z += a0.z; v0.w += a0.w;
        v1.x += a1.x; v1.y += a1.y; v1.z += a1.z; v1.w += a1.w;
    }

    float s  = v0.x + v0.y + v0.z + v0.w + v1.x + v1.y + v1.z + v1.w;
    float sq = v0.x * v0.x + v0.y * v0.y + v0.z * v0.z + v0.w * v0.w +
               v1.x * v1.x + v1.y * v1.y + v1.z * v1.z + v1.w * v1.w;
#pragma unroll
    for (int off = 16; off; off >>= 1) {
        s  += __shfl_xor_sync(0xffffffffu, s, off);
        sq += __shfl_xor_sync(0xffffffffu, sq, off);
    }
    float mu = s * (1.f / 256.f);
    float var = sq * (1.f / 256.f) - mu * mu;
    float rs = rsqrtf(var + 1e-5f);

    float4 g0 = ((const float4*)g)[lane];
    float4 b0 = ((const float4*)b)[lane];
    float4 g1 = ((const float4*)g)[lane + 32];
    float4 b1 = ((const float4*)b)[lane + 32];
    float o[8];
    o[0] = (v0.x - mu) * rs * g0.x + b0.x;
    o[1] = (v0.y - mu) * rs * g0.y + b0.y;
    o[2] = (v0.z - mu) * rs * g0.z + b0.z;
    o[3] = (v0.w - mu) * rs * g0.w + b0.w;
    o[4] = (v1.x - mu) * rs * g1.x + b1.x;
    o[5] = (v1.y - mu) * rs * g1.y + b1.y;
    o[6] = (v1.z - mu) * rs * g1.z + b1.z;
    o[7] = (v1.w - mu) * rs * g1.w + b1.w;

    long e0 = row * 256 + lane * 4;
    long e1 = row * 256 + (lane + 32) * 4;
#pragma unroll
    for (int half = 0; half < 2; half++) {
        long e = half ? e1 : e0;
        const float* ov = o + half * 4;
        *(uint32_t*)(g_xrh + e)     = pack_split_hi(ov[0], ov[1]);
        *(uint32_t*)(g_xrh + e + 2) = pack_split_hi(ov[2], ov[3]);
        *(uint32_t*)(g_xrl + e)     = pack_split_lo(ov[0], ov[1]);
        *(uint32_t*)(g_xrl + e + 2) = pack_split_lo(ov[2], ov[3]);
    }
}

// ---------------------------------------------------------------------------
// Flash attention v5 (R12, unchanged): cp.async double-buffered K/V,
// V untransposed + ldmatrix.trans, in-register softmax, 1 barrier/chunk.
// ---------------------------------------------------------------------------
constexpr int KV_BUF = 32 * AST;   // halves per plane per buffer

__global__ __launch_bounds__(256) void attention_mma5_kernel() {
    __shared__ __nv_bfloat16 sQh[128 * AST], sQl[128 * AST];
    __shared__ __nv_bfloat16 sKV[2][4][KV_BUF];   // [buf][Kh,Kl,Vh,Vl]

    int tid = threadIdx.x, lane = tid & 31, wid = tid >> 5;
    int n0 = blockIdx.x * 128, h = blockIdx.y, b = blockIdx.z;
    int g = lane >> 2, tig = lane & 3;
    const float scale = 0.17677669529663689f;   // 1/sqrt(32)

    const __nv_bfloat16* QhG = g_qh  + ((long)b * Nn + n0) * Cc + h * 32;
    const __nv_bfloat16* QlG = g_ql  + ((long)b * Nn + n0) * Cc + h * 32;
    const __nv_bfloat16* KhG = g_kvh + (long)b * Mm * Cc + h * 32;          // k2
    const __nv_bfloat16* KlG = g_kvl + (long)b * Mm * Cc + h * 32;
    const __nv_bfloat16* VhG = g_kvh + BMC + (long)b * Mm * Cc + h * 32;    // v1
    const __nv_bfloat16* VlG = g_kvl + BMC + (long)b * Mm * Cc + h * 32;

    {
        int r = tid >> 1, hf = tid & 1;
        const __nv_bfloat16* qs = QhG + (long)r * Cc + hf * 16;
        *(uint4*)&sQh[r * AST + hf * 16]     = *(const uint4*)(qs);
        *(uint4*)&sQh[r * AST + hf * 16 + 8] = *(const uint4*)(qs + 8);
        const __nv_bfloat16* qsl = QlG + (long)r * Cc + hf * 16;
        *(uint4*)&sQl[r * AST + hf * 16]     = *(const uint4*)(qsl);
        *(uint4*)&sQl[r * AST + hf * 16 + 8] = *(const uint4*)(qsl + 8);
    }

    int kvp = (tid >> 7);
    int kvo = tid & 127;
    int kvr = kvo >> 2, kvs = kvo & 3;
    const __nv_bfloat16* kG = (kvp ? KlG : KhG) + (long)kvr * Cc + kvs * 8;
    const __nv_bfloat16* vG = (kvp ? VlG : VhG) + (long)kvr * Cc + kvs * 8;
    uint32_t kS = smem_u32(&sKV[0][kvp][kvr * AST + kvs * 8]);
    uint32_t vS = smem_u32(&sKV[0][2 + kvp][kvr * AST + kvs * 8]);
    const uint32_t BUFB = (uint32_t)(4 * KV_BUF * 2);

#define ATT_ISSUE(mc_, buf_) do { \
        long co = (long)(mc_) * 32 * Cc; \
        uint32_t bo = (uint32_t)(buf_) * BUFB; \
        CP16(kS + bo, kG + co); \
        CP16(vS + bo, vG + co); \
        CP_COMMIT(); \
    } while (0)

    ATT_ISSUE(0, 0);
    __syncthreads();

    uint32_t qh[2][4], ql[2][4];
    {
        int a_row = wid * 16 + (lane & 15);
        int a_colb = (lane >> 4) << 3;
        uint32_t sq_h = smem_u32(sQh), sq_l = smem_u32(sQl);
#pragma unroll
        for (int ks = 0; ks < 2; ks++) {
            uint32_t off = (uint32_t)((a_row * AST + ks * 16 + a_colb) * 2);
            LDSM_X4(qh[ks][0], qh[ks][1], qh[ks][2], qh[ks][3], sq_h + off);
            LDSM_X4(ql[ks][0], ql[ks][1], ql[ks][2], ql[ks][3], sq_l + off);
        }
    }

    float mrun[2] = {-1e30f, -1e30f}, lrun[2] = {0.f, 0.f};
    float O[4][4];
#pragma unroll
    for (int dt = 0; dt < 4; dt++)
#pragma unroll
        for (int e = 0; e < 4; e++) O[dt][e] = 0.f;

    int b_row  = ((lane >> 4) << 3) + (lane & 7);
    int b_colb = ((lane >> 3) & 1) << 3;
    int vt_row = (((lane >> 3) & 1) << 3) + (lane & 7);
    int vt_colb = (lane >> 4) << 3;

    uint32_t kv0 = smem_u32(&sKV[0][0][0]);

    int nch = Mm / 32;
    for (int mc = 0; mc < nch; mc++) {
        CP_WAIT0();
        __syncthreads();
        if (mc + 1 < nch) ATT_ISSUE(mc + 1, (mc + 1) & 1);

        uint32_t base = kv0 + (uint32_t)(mc & 1) * BUFB;
        uint32_t sk_h = base;
        uint32_t sk_l = base + KV_BUF * 2;
        uint32_t sv_h = base + 2 * KV_BUF * 2;
        uint32_t sv_l = base + 3 * KV_BUF * 2;

        float s[4][4];
#pragma unroll
        for (int nt = 0; nt < 4; nt++)
#pragma unroll
            for (int e = 0; e < 4; e++) s[nt][e] = 0.f;

#pragma unroll
        for (int ks = 0; ks < 2; ks++) {
            uint32_t kh[4][2], kl[4][2];
#pragma unroll
            for (int grp = 0; grp < 2; grp++) {
                uint32_t off = (uint32_t)(((grp * 16 + b_row) * AST + ks * 16 + b_colb) * 2);
                uint32_t r0, r1, r2, r3;
                LDSM_X4(r0, r1, r2, r3, sk_h + off);
                kh[grp * 2][0] = r0; kh[grp * 2][1] = r1;
                kh[grp * 2 + 1][0] = r2; kh[grp * 2 + 1][1] = r3;
                LDSM_X4(r0, r1, r2, r3, sk_l + off);
                kl[grp * 2][0] = r0; kl[grp * 2][1] = r1;
                kl[grp * 2 + 1][0] = r2; kl[grp * 2 + 1][1] = r3;
            }
#pragma unroll
            for (int nt = 0; nt < 4; nt++) {
                MMA_BF16(s[nt], qh[ks], kh[nt]);
                MMA_BF16(s[nt], qh[ks], kl[nt]);
                MMA_BF16(s[nt], ql[ks], kh[nt]);
            }
        }

        float p[4][4];
#pragma unroll
        for (int rh = 0; rh < 2; rh++) {
            float mx = -1e30f;
#pragma unroll
            for (int nt = 0; nt < 4; nt++)
                mx = fmaxf(mx, fmaxf(s[nt][rh * 2] * scale,
                                     s[nt][rh * 2 + 1] * scale));
            mx = fmaxf(mx, __shfl_xor_sync(0xffffffffu, mx, 1));
            mx = fmaxf(mx, __shfl_xor_sync(0xffffffffu, mx, 2));
            float mnew = fmaxf(mrun[rh], mx);
            float alpha = __expf(mrun[rh] - mnew);
            mrun[rh] = mnew;
            float sum = 0.f;
#pragma unroll
            for (int nt = 0; nt < 4; nt++) {
                float p0 = __expf(s[nt][rh * 2] * scale - mnew);
                float p1 = __expf(s[nt][rh * 2 + 1] * scale - mnew);
                p[nt][rh * 2] = p0;
                p[nt][rh * 2 + 1] = p1;
                sum += p0 + p1;
            }
            sum += __shfl_xor_sync(0xffffffffu, sum, 1);
            sum += __shfl_xor_sync(0xffffffffu, sum, 2);
            lrun[rh] = lrun[rh] * alpha + sum;
#pragma unroll
            for (int dt = 0; dt < 4; dt++) {
                O[dt][rh * 2]     *= alpha;
                O[dt][rh * 2 + 1] *= alpha;
            }
        }

#pragma unroll
        for (int ks = 0; ks < 2; ks++) {
            uint32_t pah[4], pal[4];
            pah[0] = pack_split_hi(p[2 * ks][0], p[2 * ks][1]);
            pah[1] = pack_split_hi(p[2 * ks][2], p[2 * ks][3]);
            pah[2] = pack_split_hi(p[2 * ks + 1][0], p[2 * ks + 1][1]);
            pah[3] = pack_split_hi(p[2 * ks + 1][2], p[2 * ks + 1][3]);
            pal[0] = pack_split_lo(p[2 * ks][0], p[2 * ks][1]);
            pal[1] = pack_split_lo(p[2 * ks][2], p[2 * ks][3]);
            pal[2] = pack_split_lo(p[2 * ks + 1][0], p[2 * ks + 1][1]);
            pal[3] = pack_split_lo(p[2 * ks + 1][2], p[2 * ks + 1][3]);

            uint32_t vh[4][2], vl[4][2];
#pragma unroll
            for (int dg = 0; dg < 2; dg++) {
                uint32_t off = (uint32_t)(((ks * 16 + vt_row) * AST + dg * 16 + vt_colb) * 2);
                uint32_t r0, r1, r2, r3;
                LDSM_X4_T(r0, r1, r2, r3, sv_h + off);
                vh[dg * 2][0] = r0; vh[dg * 2][1] = r1;
                vh[dg * 2 + 1][0] = r2; vh[dg * 2 + 1][1] = r3;
                LDSM_X4_T(r0, r1, r2, r3, sv_l + off);
                vl[dg * 2][0] = r0; vl[dg * 2][1] = r1;
                vl[dg * 2 + 1][0] = r2; vl[dg * 2 + 1][1] = r3;
            }
#pragma unroll
            for (int dt = 0; dt < 4; dt++) {
                MMA_BF16(O[dt], pah, vh[dt]);
                MMA_BF16(O[dt], pah, vl[dt]);
                MMA_BF16(O[dt], pal, vh[dt]);
            }
        }
    }

    long base = ((long)b * Nn + n0) * Cc + h * 32;
#pragma unroll
    for (int rh = 0; rh < 2; rh++) {
        float inv = 1.f / lrun[rh];
        int row = wid * 16 + g + rh * 8;
#pragma unroll
        for (int dt = 0; dt < 4; dt++) {
            float ox = O[dt][rh * 2] * inv;
            float oy = O[dt][rh * 2 + 1] * inv;
            long e = base + (long)row * Cc + dt * 8 + tig * 2;
            *(uint32_t*)(g_ath + e) = pack_split_hi(ox, oy);
            *(uint32_t*)(g_atl + e) = pack_split_lo(ox, oy);
        }
    }
}

// ---------------------------------------------------------------------------
extern "C" void kernel_launch(void* const* d_in, const int* in_sizes, int n_in,
                              void* d_out, int out_size) {
    const float* x1     = (const float*)d_in[0];
    const float* x2     = (const float*)d_in[1];
    const float* q_w    = (const float*)d_in[2];
    const float* kv_w   = (const float*)d_in[3];
    const float* sr_w   = (const float*)d_in[4];
    const float* sr_b   = (const float*)d_in[5];
    const float* ln_g   = (const float*)d_in[6];
    const float* ln_b   = (const float*)d_in[7];
    const float* proj_w = (const float*)d_in[8];
    const float* proj_b = (const float*)d_in[9];
    float* out = (float*)d_out;

    cudaFuncSetAttribute(gemm_mma_kernel<true>,
                         cudaFuncAttributeMaxDynamicSharedMemorySize, GEMM_SMEM);
    cudaFuncSetAttribute(gemm_mma_kernel<false>,
                         cudaFuncAttributeMaxDynamicSharedMemorySize, GEMM_SMEM);

    float* p_xr;
    cudaGetSymbolAddress((void**)&p_xr, g_xr);
    __nv_bfloat16 *p_x1h, *p_x1l, *p_gah, *p_gal, *p_srh, *p_srl;
    __nv_bfloat16 *p_xrh, *p_xrl, *p_ath, *p_atl;
    __nv_bfloat16 *p_qh, *p_ql, *p_kvh, *p_kvl;
    __nv_bfloat16 *p_qwh, *p_qwl, *p_kwh, *p_kwl, *p_pwh, *p_pwl;
    cudaGetSymbolAddress((void**)&p_x1h, g_x1h);
    cudaGetSymbolAddress((void**)&p_x1l, g_x1l);
    cudaGetSymbolAddress((void**)&p_gah, g_gah);
    cudaGetSymbolAddress((void**)&p_gal, g_gal);
    cudaGetSymbolAddress((void**)&p_srh, g_srh);
    cudaGetSymbolAddress((void**)&p_srl, g_srl);
    cudaGetSymbolAddress((void**)&p_xrh, g_xrh);
    cudaGetSymbolAddress((void**)&p_xrl, g_xrl);
    cudaGetSymbolAddress((void**)&p_ath, g_ath);
    cudaGetSymbolAddress((void**)&p_atl, g_atl);
    cudaGetSymbolAddress((void**)&p_qh, g_qh);
    cudaGetSymbolAddress((void**)&p_ql, g_ql);
    cudaGetSymbolAddress((void**)&p_kvh, g_kvh);
    cudaGetSymbolAddress((void**)&p_kvl, g_kvl);
    cudaGetSymbolAddress((void**)&p_qwh, g_qwh);
    cudaGetSymbolAddress((void**)&p_qwl, g_qwl);
    cudaGetSymbolAddress((void**)&p_kwh, g_kwh);
    cudaGetSymbolAddress((void**)&p_kwl, g_kwl);
    cudaGetSymbolAddress((void**)&p_pwh, g_pwh);
    cudaGetSymbolAddress((void**)&p_pwl, g_pwl);

    // 1) fused prep (everything)
    prep_all_kernel<<<7424, 256>>>(sr_w, q_w, kv_w, proj_w, x1, x2);

    // 2) q = x1 @ q_w^T  -> bf16 hi/lo        [8192 x 256]
    gemm_mma_kernel<true><<<dim3(64, 4), 256, GEMM_SMEM>>>(
        p_x1h, p_x1l, p_qwh, p_qwl, nullptr, nullptr, p_qh, p_ql,
        Cc, Cc, Cc, 0, 0, 0);
    // 3) conv-as-GEMM, split-K=4 (z: K cols [0,256)/[256,512)/[512,768)/[768,1024));
    //    partials to g_xr[z*XR_PART]; bias on z==0 only.
    gemm_mma_kernel<false><<<dim3(32, 4, 4), 256, GEMM_SMEM>>>(
        p_gah, p_gal, p_srh, p_srl, sr_b, p_xr, nullptr, nullptr,
        Cc, Kc / 4, Kc, Kc / 4, Kc / 4, XR_PART);
    // 4) layernorm (sums 4 partials) -> bf16 splits
    layernorm_kernel<<<512, 256>>>(ln_g, ln_b);
    // 5) batched: z=0: k2 = x2r @ kv_w[0:256]^T ; z=1: v1 = x1r @ kv_w[256:]^T
    gemm_mma_kernel<true><<<dim3(16, 4, 2), 256, GEMM_SMEM>>>(
        p_xrh + BMC, p_xrl + BMC, p_kwh, p_kwl,
        nullptr, nullptr, p_kvh, p_kvl,
        Cc, Cc, Cc, -BMC, (long)Cc * Cc, BMC);
    // 6) flash attention v5 -> bf16 splits
    attention_mma5_kernel<<<dim3(Nn / 128, Hh, Bb), 256>>>();
    // 7) out = attn @ proj_w^T + proj_b       [8192 x 256]
    gemm_mma_kernel<false><<<dim3(64, 4), 256, GEMM_SMEM>>>(
        p_ath, p_atl, p_pwh, p_pwl, proj_b, out, nullptr, nullptr,
        Cc, Cc, Cc, 0, 0, 0);
}

// round 15
// speedup vs baseline: 1.0323x; 1.0323x over previous
#include <cuda_runtime.h>
#include <cuda_bf16.h>
#include <cstdint>
#include <math.h>

// Problem constants
constexpr int Bb = 2;
constexpr int Nn = 4096;
constexpr int Cc = 256;
constexpr int Hh = 8;
constexpr int Mm = 1024;      // reduced tokens (32x32)
constexpr int Kc = 1024;      // conv-as-GEMM K (4 * 256)
constexpr long BMC = (long)Bb * Mm * Cc;
constexpr long XR_PART = (long)2 * Bb * Mm * Cc;   // split-K partial stride

// -------- scratch (static device allocations; no cudaMalloc allowed) --------
__device__ float g_xr  [2 * 2 * Bb * Mm * Cc];  // conv partials (split-K x2)

__device__ __nv_bfloat16 g_x1h [Bb * Nn * Cc];      // x1 split
__device__ __nv_bfloat16 g_x1l [Bb * Nn * Cc];
__device__ __nv_bfloat16 g_gah [2 * Bb * Mm * Kc];  // gathered patches split
__device__ __nv_bfloat16 g_gal [2 * Bb * Mm * Kc];
__device__ __nv_bfloat16 g_srh [Cc * Kc];           // packed sr_w split
__device__ __nv_bfloat16 g_srl [Cc * Kc];
__device__ __nv_bfloat16 g_xrh [2 * Bb * Mm * Cc];  // post-LN split
__device__ __nv_bfloat16 g_xrl [2 * Bb * Mm * Cc];
__device__ __nv_bfloat16 g_qh  [Bb * Nn * Cc];      // q split (from q GEMM)
__device__ __nv_bfloat16 g_ql  [Bb * Nn * Cc];
__device__ __nv_bfloat16 g_kvh [2 * Bb * Mm * Cc];  // [0]: k2, [1]: v1  (hi)
__device__ __nv_bfloat16 g_kvl [2 * Bb * Mm * Cc];  // (lo)
__device__ __nv_bfloat16 g_ath [Bb * Nn * Cc];      // attention out split
__device__ __nv_bfloat16 g_atl [Bb * Nn * Cc];
__device__ __nv_bfloat16 g_qwh [Cc * Cc];
__device__ __nv_bfloat16 g_qwl [Cc * Cc];
__device__ __nv_bfloat16 g_kwh [2 * Cc * Cc];
__device__ __nv_bfloat16 g_kwl [2 * Cc * Cc];
__device__ __nv_bfloat16 g_pwh [Cc * Cc];
__device__ __nv_bfloat16 g_pwl [Cc * Cc];

// ---------------------------------------------------------------------------
__device__ __forceinline__ uint32_t smem_u32(const void* p) {
    uint32_t a;
    asm("{ .reg .u64 t; cvta.to.shared.u64 t, %1; cvt.u32.u64 %0, t; }"
        : "=r"(a) : "l"(p));
    return a;
}
__device__ __forceinline__ void split2(float v, __nv_bfloat16& h, __nv_bfloat16& l) {
    h = __float2bfloat16(v);
    l = __float2bfloat16(v - __bfloat162float(h));
}
__device__ __forceinline__ uint32_t pack_split_hi(float a, float b) {
    __nv_bfloat162 p;
    p.x = __float2bfloat16(a);
    p.y = __float2bfloat16(b);
    return *(uint32_t*)&p;
}
__device__ __forceinline__ uint32_t pack_split_lo(float a, float b) {
    __nv_bfloat162 p;
    p.x = __float2bfloat16(a - __bfloat162float(__float2bfloat16(a)));
    p.y = __float2bfloat16(b - __bfloat162float(__float2bfloat16(b)));
    return *(uint32_t*)&p;
}
__device__ __forceinline__ void split4_at(const float* __restrict__ in,
                                          __nv_bfloat16* __restrict__ oh,
                                          __nv_bfloat16* __restrict__ ol, int idx) {
    float4 v = ((const float4*)in)[idx];
    ((uint32_t*)oh)[idx * 2]     = pack_split_hi(v.x, v.y);
    ((uint32_t*)oh)[idx * 2 + 1] = pack_split_hi(v.z, v.w);
    ((uint32_t*)ol)[idx * 2]     = pack_split_lo(v.x, v.y);
    ((uint32_t*)ol)[idx * 2 + 1] = pack_split_lo(v.z, v.w);
}

#define LDSM_X4(r0, r1, r2, r3, addr) \
    asm volatile("ldmatrix.sync.aligned.m8n8.x4.shared.b16 {%0,%1,%2,%3}, [%4];" \
                 : "=r"(r0), "=r"(r1), "=r"(r2), "=r"(r3) : "r"(addr))

#define LDSM_X4_T(r0, r1, r2, r3, addr) \
    asm volatile("ldmatrix.sync.aligned.m8n8.x4.trans.shared.b16 {%0,%1,%2,%3}, [%4];" \
                 : "=r"(r0), "=r"(r1), "=r"(r2), "=r"(r3) : "r"(addr))

#define MMA_BF16(c, a, b) \
    asm volatile("mma.sync.aligned.m16n8k16.row.col.f32.bf16.bf16.f32 " \
                 "{%0,%1,%2,%3}, {%4,%5,%6,%7}, {%8,%9}, {%0,%1,%2,%3};" \
                 : "+f"((c)[0]), "+f"((c)[1]), "+f"((c)[2]), "+f"((c)[3]) \
                 : "r"((a)[0]), "r"((a)[1]), "r"((a)[2]), "r"((a)[3]), \
                   "r"((b)[0]), "r"((b)[1]))

#define CP16(s, g) \
    asm volatile("cp.async.cg.shared.global [%0], [%1], 16;" :: "r"(s), "l"(g))
#define CP_COMMIT() asm volatile("cp.async.commit_group;" ::: "memory")
#define CP_WAIT0()  asm volatile("cp.async.wait_group 0;" ::: "memory")

// ---------------------------------------------------------------------------
// Fused prep: pack+split sr_w, split q_w/kv_w/proj_w, gather patches,
// split x1. One launch, 7424 blocks.
// ---------------------------------------------------------------------------
__global__ void prep_all_kernel(const float* __restrict__ srw,
                                const float* __restrict__ qw,
                                const float* __restrict__ kvw,
                                const float* __restrict__ pw,
                                const float* __restrict__ x1,
                                const float* __restrict__ x2) {
    int bx = blockIdx.x, t = threadIdx.x;
    if (bx < 1024) {                       // pack sr_w
        int idx = bx * 256 + t;
        int co = idx >> 10;
        int k  = idx & 1023;
        int seg = k >> 8;
        int ci  = k & 255;
        float v = srw[((co << 8) + ci) * 4 + seg];
        __nv_bfloat16 h, l;
        split2(v, h, l);
        g_srh[idx] = h;
        g_srl[idx] = l;
    } else if (bx < 1088) {
        split4_at(qw, g_qwh, g_qwl, (bx - 1024) * 256 + t);
    } else if (bx < 1216) {
        split4_at(kvw, g_kwh, g_kwl, (bx - 1088) * 256 + t);
    } else if (bx < 1280) {
        split4_at(pw, g_pwh, g_pwl, (bx - 1216) * 256 + t);
    } else if (bx < 5376) {                // gather conv patches
        unsigned idx = (bx - 1280) * 256 + t;
        int k4  = idx & 255;
        int m   = (idx >> 8) & 1023;
        int b   = (idx >> 18) & 1;
        int src = (idx >> 19) & 1;
        int seg = k4 >> 6;
        int ci4 = k4 & 63;
        int i = m >> 5, j = m & 31;
        int kh = seg >> 1, kw = seg & 1;
        int n = (2 * i + kh) * 64 + 2 * j + kw;
        const float* sp = src ? x2 : x1;
        float4 v = *(const float4*)(sp + ((long)b * Nn + n) * Cc + ci4 * 4);
        ((uint32_t*)g_gah)[idx * 2]     = pack_split_hi(v.x, v.y);
        ((uint32_t*)g_gah)[idx * 2 + 1] = pack_split_hi(v.z, v.w);
        ((uint32_t*)g_gal)[idx * 2]     = pack_split_lo(v.x, v.y);
        ((uint32_t*)g_gal)[idx * 2 + 1] = pack_split_lo(v.z, v.w);
    } else {                               // split x1
        split4_at(x1, g_x1h, g_x1l, (bx - 5376) * 256 + t);
    }
}

// ---------------------------------------------------------------------------
// GEMM body (R12-validated): CTA tile 128x64, cp.async double-buffered,
// one barrier per chunk. Runtime `split` selects fp32 vs bf16 hi/lo output.
// ---------------------------------------------------------------------------
constexpr int AST = 40;             // smem stride in halves (80B rows)
constexpr int GA_BUF = 128 * AST;   // 5120 halves per A buffer
constexpr int GW_BUF = 64 * AST;    // 2560 halves per W buffer
constexpr int SM_AL = 2 * GA_BUF;
constexpr int SM_WH = 4 * GA_BUF;
constexpr int SM_WL = SM_WH + 2 * GW_BUF;
constexpr int SM_BIAS_H = SM_WL + 2 * GW_BUF;        // 30720 halves
constexpr int GEMM_SMEM = SM_BIAS_H * 2 + 64 * 4;    // 61696 bytes

__device__ __forceinline__ void gemm_body(
    const __nv_bfloat16* __restrict__ Ah, const __nv_bfloat16* __restrict__ Al,
    const __nv_bfloat16* __restrict__ Wh, const __nv_bfloat16* __restrict__ Wl,
    const float* __restrict__ bias, float* __restrict__ Cout,
    __nv_bfloat16* __restrict__ Ch, __nv_bfloat16* __restrict__ Cl,
    int Ndim, int Kext, int Kstride, int m0, int n0, bool split)
{
    extern __shared__ __nv_bfloat16 smem[];
    float* sbias = (float*)(smem + SM_BIAS_H);

    int tid = threadIdx.x, lane = tid & 31, wid = tid >> 5;
    int wm = wid >> 1, wn = wid & 1;

    if (tid < 64) sbias[tid] = bias ? bias[n0 + tid] : 0.f;

    float acc[2][4][4];
#pragma unroll
    for (int mt = 0; mt < 2; mt++)
#pragma unroll
        for (int nt = 0; nt < 4; nt++)
#pragma unroll
            for (int e = 0; e < 4; e++) acc[mt][nt][e] = 0.f;

    int a_row  = wm * 32 + (lane & 15);
    int a_colb = (lane >> 4) << 3;
    int b_row  = wn * 32 + ((lane >> 4) << 3) + (lane & 7);
    int b_colb = ((lane >> 3) & 1) << 3;

    uint32_t sb = smem_u32(smem);

    int ar = tid >> 1, ahalf = tid & 1;
    int brr = tid >> 2, bq = tid & 3;

    const __nv_bfloat16* gAh = Ah + (size_t)(m0 + ar) * Kstride + ahalf * 16;
    const __nv_bfloat16* gAl = Al + (size_t)(m0 + ar) * Kstride + ahalf * 16;
    const __nv_bfloat16* gWh = Wh + (size_t)(n0 + brr) * Kstride + bq * 8;
    const __nv_bfloat16* gWl = Wl + (size_t)(n0 + brr) * Kstride + bq * 8;

    uint32_t sAh0 = sb + (ar * AST + ahalf * 16) * 2;
    uint32_t sAl0 = sb + (SM_AL + ar * AST + ahalf * 16) * 2;
    uint32_t sWh0 = sb + (SM_WH + brr * AST + bq * 8) * 2;
    uint32_t sWl0 = sb + (SM_WL + brr * AST + bq * 8) * 2;

#define GEMM_ISSUE(k0, buf) do { \
        uint32_t ao = (uint32_t)(buf) * GA_BUF * 2; \
        uint32_t wo = (uint32_t)(buf) * GW_BUF * 2; \
        CP16(sAh0 + ao,      gAh + (k0)); \
        CP16(sAh0 + ao + 16, gAh + (k0) + 8); \
        CP16(sAl0 + ao,      gAl + (k0)); \
        CP16(sAl0 + ao + 16, gAl + (k0) + 8); \
        CP16(sWh0 + wo,      gWh + (k0)); \
        CP16(sWl0 + wo,      gWl + (k0)); \
        CP_COMMIT(); \
    } while (0)

    GEMM_ISSUE(0, 0);

    int nch = Kext >> 5;
    for (int ch = 0; ch < nch; ch++) {
        CP_WAIT0();
        __syncthreads();
        if (ch + 1 < nch) GEMM_ISSUE((ch + 1) * 32, (ch + 1) & 1);

        int buf = ch & 1;
        uint32_t sa_h = sb + (uint32_t)buf * GA_BUF * 2;
        uint32_t sa_l = sb + (SM_AL + buf * GA_BUF) * 2;
        uint32_t sb_h = sb + (SM_WH + buf * GW_BUF) * 2;
        uint32_t sb_l = sb + (SM_WL + buf * GW_BUF) * 2;

#pragma unroll
        for (int ks = 0; ks < 32; ks += 16) {
            uint32_t aH[2][4], aL[2][4], bH[4][2], bL[4][2];
#pragma unroll
            for (int mt = 0; mt < 2; mt++) {
                uint32_t off = (uint32_t)(((a_row + mt * 16) * AST + ks + a_colb) * 2);
                LDSM_X4(aH[mt][0], aH[mt][1], aH[mt][2], aH[mt][3], sa_h + off);
                LDSM_X4(aL[mt][0], aL[mt][1], aL[mt][2], aL[mt][3], sa_l + off);
            }
#pragma unroll
            for (int p = 0; p < 2; p++) {
                uint32_t off = (uint32_t)(((b_row + p * 16) * AST + ks + b_colb) * 2);
                uint32_t r0, r1, r2, r3;
                LDSM_X4(r0, r1, r2, r3, sb_h + off);
                bH[p * 2][0] = r0; bH[p * 2][1] = r1;
                bH[p * 2 + 1][0] = r2; bH[p * 2 + 1][1] = r3;
                LDSM_X4(r0, r1, r2, r3, sb_l + off);
                bL[p * 2][0] = r0; bL[p * 2][1] = r1;
                bL[p * 2 + 1][0] = r2; bL[p * 2 + 1][1] = r3;
            }
#pragma unroll
            for (int mt = 0; mt < 2; mt++)
#pragma unroll
                for (int nt = 0; nt < 4; nt++) {
                    MMA_BF16(acc[mt][nt], aH[mt], bH[nt]);
                    MMA_BF16(acc[mt][nt], aH[mt], bL[nt]);
                    MMA_BF16(acc[mt][nt], aL[mt], bH[nt]);
                }
        }
    }

    int g = lane >> 2, tig = lane & 3;
#pragma unroll
    for (int mt = 0; mt < 2; mt++)
#pragma unroll
        for (int hf = 0; hf < 2; hf++) {
            int row = m0 + wm * 32 + mt * 16 + g + hf * 8;
#pragma unroll
            for (int nt = 0; nt < 4; nt++) {
                int cb = wn * 32 + nt * 8 + tig * 2;
                float ox = acc[mt][nt][hf * 2 + 0] + sbias[cb];
                float oy = acc[mt][nt][hf * 2 + 1] + sbias[cb + 1];
                size_t e = (size_t)row * Ndim + n0 + cb;
                if (split) {
                    *(uint32_t*)(Ch + e) = pack_split_hi(ox, oy);
                    *(uint32_t*)(Cl + e) = pack_split_lo(ox, oy);
                } else {
                    float2 o; o.x = ox; o.y = oy;
                    *(float2*)(Cout + e) = o;
                }
            }
        }
#undef GEMM_ISSUE
}

// Fused q-proj + conv launch: z in {0,1} = conv split-K slices (bx<32),
// z == 2 = q-GEMM (all 64 bx). Early-exit CTAs leave before any barrier.
__global__ __launch_bounds__(256) void qconv_kernel(const float* sr_b) {
    int z = blockIdx.z;
    int m0 = blockIdx.x * 128, n0 = blockIdx.y * 64;
    if (z < 2) {
        if (blockIdx.x >= 32) return;
        int ko = z * (Kc / 2);
        gemm_body(g_gah + ko, g_gal + ko, g_srh + ko, g_srl + ko,
                  z == 0 ? sr_b : nullptr, g_xr + (long)z * XR_PART,
                  nullptr, nullptr, Cc, Kc / 2, Kc, m0, n0, false);
    } else {
        gemm_body(g_x1h, g_x1l, g_qwh, g_qwl, nullptr, nullptr,
                  g_qh, g_ql, Cc, Cc, Cc, m0, n0, true);
    }
}

// Generic GEMM kernel (kv batched + out-proj).
template <bool SPLIT>
__global__ __launch_bounds__(256) void gemm_mma_kernel(
    const __nv_bfloat16* __restrict__ Ah, const __nv_bfloat16* __restrict__ Al,
    const __nv_bfloat16* __restrict__ Wh, const __nv_bfloat16* __restrict__ Wl,
    const float* __restrict__ bias, float* __restrict__ Cout,
    __nv_bfloat16* __restrict__ Ch, __nv_bfloat16* __restrict__ Cl,
    int Ndim, int Kext, int Kstride, long sA, long sW, long sC)
{
    long zo = (long)blockIdx.z;
    gemm_body(Ah + zo * sA, Al + zo * sA, Wh + zo * sW, Wl + zo * sW,
              (blockIdx.z == 0) ? bias : nullptr,
              SPLIT ? nullptr : Cout + zo * sC,
              SPLIT ? Ch + zo * sC : nullptr,
              SPLIT ? Cl + zo * sC : nullptr,
              Ndim, Kext, Kstride,
              blockIdx.x * 128, blockIdx.y * 64, SPLIT);
}

// ---------------------------------------------------------------------------
// LayerNorm over rows (4096 x 256); sums 2 split-K conv partials, -> splits.
// ---------------------------------------------------------------------------
__global__ __launch_bounds__(256) void layernorm_kernel(
    const float* __restrict__ g, const float* __restrict__ b)
{
    int warp = threadIdx.x >> 5, lane = threadIdx.x & 31;
    long row = (long)blockIdx.x * 8 + warp;
    const float* p0 = g_xr + row * 256;
    const float* p1 = g_xr + XR_PART + row * 256;

    float4 a0 = ((const float4*)p0)[lane];
    float4 a1 = ((const float4*)p0)[lane + 32];
    float4 c0 = ((const float4*)p1)[lane];
    float4 c1 = ((const float4*)p1)[lane + 32];
    float4 v0, v1;
    v0.x = a0.x + c0.x; v0.y = a0.y + c0.y; v0.z = a0.z + c0.z; v0.w = a0.w + c0.w;
    v1.x = a1.x + c1.x; v1.y = a1.y + c1.y; v1.z = a1.z + c1.z; v1.w = a1.w + c1.w;

    float s  = v0.x + v0.y + v0.z + v0.w + v1.x + v1.y + v1.z + v1.w;
    float sq = v0.x * v0.x + v0.y * v0.y + v0.z * v0.z + v0.w * v0.w +
               v1.x * v1.x + v1.y * v1.y + v1.z * v1.z + v1.w * v1.w;
#pragma unroll
    for (int off = 16; off; off >>= 1) {
        s  += __shfl_xor_sync(0xffffffffu, s, off);
        sq += __shfl_xor_sync(0xffffffffu, sq, off);
    }
    float mu = s * (1.f / 256.f);
    float var = sq * (1.f / 256.f) - mu * mu;
    float rs = rsqrtf(var + 1e-5f);

    float4 g0 = ((const float4*)g)[lane];
    float4 b0 = ((const float4*)b)[lane];
    float4 g1 = ((const float4*)g)[lane + 32];
    float4 b1 = ((const float4*)b)[lane + 32];
    float o[8];
    o[0] = (v0.x - mu) * rs * g0.x + b0.x;
    o[1] = (v0.y - mu) * rs * g0.y + b0.y;
    o[2] = (v0.z - mu) * rs * g0.z + b0.z;
    o[3] = (v0.w - mu) * rs * g0.w + b0.w;
    o[4] = (v1.x - mu) * rs * g1.x + b1.x;
    o[5] = (v1.y - mu) * rs * g1.y + b1.y;
    o[6] = (v1.z - mu) * rs * g1.z + b1.z;
    o[7] = (v1.w - mu) * rs * g1.w + b1.w;

    long e0 = row * 256 + lane * 4;
    long e1 = row * 256 + (lane + 32) * 4;
#pragma unroll
    for (int half = 0; half < 2; half++) {
        long e = half ? e1 : e0;
        const float* ov = o + half * 4;
        *(uint32_t*)(g_xrh + e)     = pack_split_hi(ov[0], ov[1]);
        *(uint32_t*)(g_xrh + e + 2) = pack_split_hi(ov[2], ov[3]);
        *(uint32_t*)(g_xrl + e)     = pack_split_lo(ov[0], ov[1]);
        *(uint32_t*)(g_xrl + e + 2) = pack_split_lo(ov[2], ov[3]);
    }
}

// ---------------------------------------------------------------------------
// Flash attention v5 (R12, unchanged): cp.async double-buffered K/V,
// V untransposed + ldmatrix.trans, in-register softmax, 1 barrier/chunk.
// ---------------------------------------------------------------------------
constexpr int KV_BUF = 32 * AST;   // halves per plane per buffer

__global__ __launch_bounds__(256) void attention_mma5_kernel() {
    __shared__ __nv_bfloat16 sQh[128 * AST], sQl[128 * AST];
    __shared__ __nv_bfloat16 sKV[2][4][KV_BUF];   // [buf][Kh,Kl,Vh,Vl]

    int tid = threadIdx.x, lane = tid & 31, wid = tid >> 5;
    int n0 = blockIdx.x * 128, h = blockIdx.y, b = blockIdx.z;
    int g = lane >> 2, tig = lane & 3;
    const float scale = 0.17677669529663689f;   // 1/sqrt(32)

    const __nv_bfloat16* QhG = g_qh  + ((long)b * Nn + n0) * Cc + h * 32;
    const __nv_bfloat16* QlG = g_ql  + ((long)b * Nn + n0) * Cc + h * 32;
    const __nv_bfloat16* KhG = g_kvh + (long)b * Mm * Cc + h * 32;          // k2
    const __nv_bfloat16* KlG = g_kvl + (long)b * Mm * Cc + h * 32;
    const __nv_bfloat16* VhG = g_kvh + BMC + (long)b * Mm * Cc + h * 32;    // v1
    const __nv_bfloat16* VlG = g_kvl + BMC + (long)b * Mm * Cc + h * 32;

    {
        int r = tid >> 1, hf = tid & 1;
        const __nv_bfloat16* qs = QhG + (long)r * Cc + hf * 16;
        *(uint4*)&sQh[r * AST + hf * 16]     = *(const uint4*)(qs);
        *(uint4*)&sQh[r * AST + hf * 16 + 8] = *(const uint4*)(qs + 8);
        const __nv_bfloat16* qsl = QlG + (long)r * Cc + hf * 16;
        *(uint4*)&sQl[r * AST + hf * 16]     = *(const uint4*)(qsl);
        *(uint4*)&sQl[r * AST + hf * 16 + 8] = *(const uint4*)(qsl + 8);
    }

    int kvp = (tid >> 7);
    int kvo = tid & 127;
    int kvr = kvo >> 2, kvs = kvo & 3;
    const __nv_bfloat16* kG = (kvp ? KlG : KhG) + (long)kvr * Cc + kvs * 8;
    const __nv_bfloat16* vG = (kvp ? VlG : VhG) + (long)kvr * Cc + kvs * 8;
    uint32_t kS = smem_u32(&sKV[0][kvp][kvr * AST + kvs * 8]);
    uint32_t vS = smem_u32(&sKV[0][2 + kvp][kvr * AST + kvs * 8]);
    const uint32_t BUFB = (uint32_t)(4 * KV_BUF * 2);

#define ATT_ISSUE(mc_, buf_) do { \
        long co = (long)(mc_) * 32 * Cc; \
        uint32_t bo = (uint32_t)(buf_) * BUFB; \
        CP16(kS + bo, kG + co); \
        CP16(vS + bo, vG + co); \
        CP_COMMIT(); \
    } while (0)

    ATT_ISSUE(0, 0);
    __syncthreads();

    uint32_t qh[2][4], ql[2][4];
    {
        int a_row = wid * 16 + (lane & 15);
        int a_colb = (lane >> 4) << 3;
        uint32_t sq_h = smem_u32(sQh), sq_l = smem_u32(sQl);
#pragma unroll
        for (int ks = 0; ks < 2; ks++) {
            uint32_t off = (uint32_t)((a_row * AST + ks * 16 + a_colb) * 2);
            LDSM_X4(qh[ks][0], qh[ks][1], qh[ks][2], qh[ks][3], sq_h + off);
            LDSM_X4(ql[ks][0], ql[ks][1], ql[ks][2], ql[ks][3], sq_l + off);
        }
    }

    float mrun[2] = {-1e30f, -1e30f}, lrun[2] = {0.f, 0.f};
    float O[4][4];
#pragma unroll
    for (int dt = 0; dt < 4; dt++)
#pragma unroll
        for (int e = 0; e < 4; e++) O[dt][e] = 0.f;

    int b_row  = ((lane >> 4) << 3) + (lane & 7);
    int b_colb = ((lane >> 3) & 1) << 3;
    int vt_row = (((lane >> 3) & 1) << 3) + (lane & 7);
    int vt_colb = (lane >> 4) << 3;

    uint32_t kv0 = smem_u32(&sKV[0][0][0]);

    int nch = Mm / 32;
    for (int mc = 0; mc < nch; mc++) {
        CP_WAIT0();
        __syncthreads();
        if (mc + 1 < nch) ATT_ISSUE(mc + 1, (mc + 1) & 1);

        uint32_t base = kv0 + (uint32_t)(mc & 1) * BUFB;
        uint32_t sk_h = base;
        uint32_t sk_l = base + KV_BUF * 2;
        uint32_t sv_h = base + 2 * KV_BUF * 2;
        uint32_t sv_l = base + 3 * KV_BUF * 2;

        float s[4][4];
#pragma unroll
        for (int nt = 0; nt < 4; nt++)
#pragma unroll
            for (int e = 0; e < 4; e++) s[nt][e] = 0.f;

#pragma unroll
        for (int ks = 0; ks < 2; ks++) {
            uint32_t kh[4][2], kl[4][2];
#pragma unroll
            for (int grp = 0; grp < 2; grp++) {
                uint32_t off = (uint32_t)(((grp * 16 + b_row) * AST + ks * 16 + b_colb) * 2);
                uint32_t r0, r1, r2, r3;
                LDSM_X4(r0, r1, r2, r3, sk_h + off);
                kh[grp * 2][0] = r0; kh[grp * 2][1] = r1;
                kh[grp * 2 + 1][0] = r2; kh[grp * 2 + 1][1] = r3;
                LDSM_X4(r0, r1, r2, r3, sk_l + off);
                kl[grp * 2][0] = r0; kl[grp * 2][1] = r1;
                kl[grp * 2 + 1][0] = r2; kl[grp * 2 + 1][1] = r3;
            }
#pragma unroll
            for (int nt = 0; nt < 4; nt++) {
                MMA_BF16(s[nt], qh[ks], kh[nt]);
                MMA_BF16(s[nt], qh[ks], kl[nt]);
                MMA_BF16(s[nt], ql[ks], kh[nt]);
            }
        }

        float p[4][4];
#pragma unroll
        for (int rh = 0; rh < 2; rh++) {
            float mx = -1e30f;
#pragma unroll
            for (int nt = 0; nt < 4; nt++)
                mx = fmaxf(mx, fmaxf(s[nt][rh * 2] * scale,
                                     s[nt][rh * 2 + 1] * scale));
            mx = fmaxf(mx, __shfl_xor_sync(0xffffffffu, mx, 1));
            mx = fmaxf(mx, __shfl_xor_sync(0xffffffffu, mx, 2));
            float mnew = fmaxf(mrun[rh], mx);
            float alpha = __expf(mrun[rh] - mnew);
            mrun[rh] = mnew;
            float sum = 0.f;
#pragma unroll
            for (int nt = 0; nt < 4; nt++) {
                float p0 = __expf(s[nt][rh * 2] * scale - mnew);
                float p1 = __expf(s[nt][rh * 2 + 1] * scale - mnew);
                p[nt][rh * 2] = p0;
                p[nt][rh * 2 + 1] = p1;
                sum += p0 + p1;
            }
            sum += __shfl_xor_sync(0xffffffffu, sum, 1);
            sum += __shfl_xor_sync(0xffffffffu, sum, 2);
            lrun[rh] = lrun[rh] * alpha + sum;
#pragma unroll
            for (int dt = 0; dt < 4; dt++) {
                O[dt][rh * 2]     *= alpha;
                O[dt][rh * 2 + 1] *= alpha;
            }
        }

#pragma unroll
        for (int ks = 0; ks < 2; ks++) {
            uint32_t pah[4], pal[4];
            pah[0] = pack_split_hi(p[2 * ks][0], p[2 * ks][1]);
            pah[1] = pack_split_hi(p[2 * ks][2], p[2 * ks][3]);
            pah[2] = pack_split_hi(p[2 * ks + 1][0], p[2 * ks + 1][1]);
            pah[3] = pack_split_hi(p[2 * ks + 1][2], p[2 * ks + 1][3]);
            pal[0] = pack_split_lo(p[2 * ks][0], p[2 * ks][1]);
            pal[1] = pack_split_lo(p[2 * ks][2], p[2 * ks][3]);
            pal[2] = pack_split_lo(p[2 * ks + 1][0], p[2 * ks + 1][1]);
            pal[3] = pack_split_lo(p[2 * ks + 1][2], p[2 * ks + 1][3]);

            uint32_t vh[4][2], vl[4][2];
#pragma unroll
            for (int dg = 0; dg < 2; dg++) {
                uint32_t off = (uint32_t)(((ks * 16 + vt_row) * AST + dg * 16 + vt_colb) * 2);
                uint32_t r0, r1, r2, r3;
                LDSM_X4_T(r0, r1, r2, r3, sv_h + off);
                vh[dg * 2][0] = r0; vh[dg * 2][1] = r1;
                vh[dg * 2 + 1][0] = r2; vh[dg * 2 + 1][1] = r3;
                LDSM_X4_T(r0, r1, r2, r3, sv_l + off);
                vl[dg * 2][0] = r0; vl[dg * 2][1] = r1;
                vl[dg * 2 + 1][0] = r2; vl[dg * 2 + 1][1] = r3;
            }
#pragma unroll
            for (int dt = 0; dt < 4; dt++) {
                MMA_BF16(O[dt], pah, vh[dt]);
                MMA_BF16(O[dt], pah, vl[dt]);
                MMA_BF16(O[dt], pal, vh[dt]);
            }
        }
    }

    long base = ((long)b * Nn + n0) * Cc + h * 32;
#pragma unroll
    for (int rh = 0; rh < 2; rh++) {
        float inv = 1.f / lrun[rh];
        int row = wid * 16 + g + rh * 8;
#pragma unroll
        for (int dt = 0; dt < 4; dt++) {
            float ox = O[dt][rh * 2] * inv;
            float oy = O[dt][rh * 2 + 1] * inv;
            long e = base + (long)row * Cc + dt * 8 + tig * 2;
            *(uint32_t*)(g_ath + e) = pack_split_hi(ox, oy);
            *(uint32_t*)(g_atl + e) = pack_split_lo(ox, oy);
        }
    }
}

// ---------------------------------------------------------------------------
extern "C" void kernel_launch(void* const* d_in, const int* in_sizes, int n_in,
                              void* d_out, int out_size) {
    const float* x1     = (const float*)d_in[0];
    const float* x2     = (const float*)d_in[1];
    const float* q_w    = (const float*)d_in[2];
    const float* kv_w   = (const float*)d_in[3];
    const float* sr_w   = (const float*)d_in[4];
    const float* sr_b   = (const float*)d_in[5];
    const float* ln_g   = (const float*)d_in[6];
    const float* ln_b   = (const float*)d_in[7];
    const float* proj_w = (const float*)d_in[8];
    const float* proj_b = (const float*)d_in[9];
    float* out = (float*)d_out;

    cudaFuncSetAttribute(qconv_kernel,
                         cudaFuncAttributeMaxDynamicSharedMemorySize, GEMM_SMEM);
    cudaFuncSetAttribute(gemm_mma_kernel<true>,
                         cudaFuncAttributeMaxDynamicSharedMemorySize, GEMM_SMEM);
    cudaFuncSetAttribute(gemm_mma_kernel<false>,
                         cudaFuncAttributeMaxDynamicSharedMemorySize, GEMM_SMEM);

    __nv_bfloat16 *p_xrh, *p_xrl, *p_ath, *p_atl, *p_kvh, *p_kvl;
    __nv_bfloat16 *p_kwh, *p_kwl, *p_pwh, *p_pwl;
    cudaGetSymbolAddress((void**)&p_xrh, g_xrh);
    cudaGetSymbolAddress((void**)&p_xrl, g_xrl);
    cudaGetSymbolAddress((void**)&p_ath, g_ath);
    cudaGetSymbolAddress((void**)&p_atl, g_atl);
    cudaGetSymbolAddress((void**)&p_kvh, g_kvh);
    cudaGetSymbolAddress((void**)&p_kvl, g_kvl);
    cudaGetSymbolAddress((void**)&p_kwh, g_kwh);
    cudaGetSymbolAddress((void**)&p_kwl, g_kwl);
    cudaGetSymbolAddress((void**)&p_pwh, g_pwh);
    cudaGetSymbolAddress((void**)&p_pwl, g_pwl);

    // 1) fused prep (everything)
    prep_all_kernel<<<7424, 256>>>(sr_w, q_w, kv_w, proj_w, x1, x2);

    // 2+3) fused: z<2 conv split-K=2 slices; z==2 q-GEMM. grid (64,4,3).
    qconv_kernel<<<dim3(64, 4, 3), 256, GEMM_SMEM>>>(sr_b);

    // 4) layernorm (sums 2 partials) -> bf16 splits
    layernorm_kernel<<<512, 256>>>(ln_g, ln_b);
    // 5) batched: z=0: k2 = x2r @ kv_w[0:256]^T ; z=1: v1 = x1r @ kv_w[256:]^T
    gemm_mma_kernel<true><<<dim3(16, 4, 2), 256, GEMM_SMEM>>>(
        p_xrh + BMC, p_xrl + BMC, p_kwh, p_kwl,
        nullptr, nullptr, p_kvh, p_kvl,
        Cc, Cc, Cc, -BMC, (long)Cc * Cc, BMC);
    // 6) flash attention v5 -> bf16 splits
    attention_mma5_kernel<<<dim3(Nn / 128, Hh, Bb), 256>>>();
    // 7) out = attn @ proj_w^T + proj_b
    gemm_mma_kernel<false><<<dim3(64, 4), 256, GEMM_SMEM>>>(
        p_ath, p_atl, p_pwh, p_pwl, proj_b, out, nullptr, nullptr,
        Cc, Cc, Cc, 0, 0, 0);
}